// round 11
// baseline (speedup 1.0000x reference)
#include <cuda_runtime.h>
#include <stdint.h>

// RT-DETR post-processing, GB300 sm_103a.
// d_in[0]: pred_logits  float32 [256, 1000, 80]
// d_in[1]: pred_boxes   float32 [256, 1000, 4]   (cx, cy, w, h)
// d_in[2]: target_sizes float32 [256, 2]         (img_h, img_w)
// Output float32 concat: [scores 256*300 | labels 256*300 | boxes 256*300*4]

#define NB   256
#define NQ   1000
#define TOPK 300
typedef unsigned long long ull;

__device__ ull g_keys[NB * NQ];

// ---------------------------------------------------------------------------
// Kernel 1: 8 queries per warp. 5 coalesced LDG.128 staged in registers,
// smem transpose, group-of-4-lanes per query. Exact (max value, min class)
// via packed 64-bit reduction.
// ---------------------------------------------------------------------------
__global__ void __launch_bounds__(256) score_kernel(const float* __restrict__ logits) {
    __shared__ float4 sh[8][160];          // 8 warps x 8 queries x 20 f4
    int wid  = threadIdx.x >> 5;
    int lane = threadIdx.x & 31;
    int b    = blockIdx.y;
    int q0   = blockIdx.x * 64 + wid * 8;
    if (q0 >= NQ) return;                  // tail warps of last block

    const float4* p = (const float4*)logits + ((size_t)b * NQ + q0) * 20 + lane;
    float4 a0 = p[0], a1 = p[32], a2 = p[64], a3 = p[96], a4 = p[128];
    sh[wid][lane      ] = a0;
    sh[wid][lane +  32] = a1;
    sh[wid][lane +  64] = a2;
    sh[wid][lane +  96] = a3;
    sh[wid][lane + 128] = a4;
    __syncwarp();

    int g = lane >> 2, j = lane & 3;
    const float4* q = &sh[wid][g * 20 + j];
    float4 w0 = q[0], w1 = q[4], w2 = q[8], w3 = q[12], w4 = q[16];

    float m = fmaxf(fmaxf(fmaxf(fmaxf(fmaxf(w0.x, w0.y), fmaxf(w0.z, w0.w)),
                                fmaxf(fmaxf(w1.x, w1.y), fmaxf(w1.z, w1.w))),
                          fmaxf(fmaxf(fmaxf(w2.x, w2.y), fmaxf(w2.z, w2.w)),
                                fmaxf(fmaxf(w3.x, w3.y), fmaxf(w3.z, w3.w)))),
                    fmaxf(fmaxf(w4.x, w4.y), fmaxf(w4.z, w4.w)));

    // Per-lane lowest class among maxima (reverse-overwrite scan).
    // class of element e of chunk i = 4*j + 16*i + e.
    int cls = 0;
    {
        int cb = 4 * j;
        if (w4.w == m) cls = cb + 64 + 3;
        if (w4.z == m) cls = cb + 64 + 2;
        if (w4.y == m) cls = cb + 64 + 1;
        if (w4.x == m) cls = cb + 64;
        if (w3.w == m) cls = cb + 48 + 3;
        if (w3.z == m) cls = cb + 48 + 2;
        if (w3.y == m) cls = cb + 48 + 1;
        if (w3.x == m) cls = cb + 48;
        if (w2.w == m) cls = cb + 32 + 3;
        if (w2.z == m) cls = cb + 32 + 2;
        if (w2.y == m) cls = cb + 32 + 1;
        if (w2.x == m) cls = cb + 32;
        if (w1.w == m) cls = cb + 16 + 3;
        if (w1.z == m) cls = cb + 16 + 2;
        if (w1.y == m) cls = cb + 16 + 1;
        if (w1.x == m) cls = cb + 16;
        if (w0.w == m) cls = cb + 3;
        if (w0.z == m) cls = cb + 2;
        if (w0.y == m) cls = cb + 1;
        if (w0.x == m) cls = cb;
    }

    unsigned t  = __float_as_uint(m);
    unsigned u0 = t ^ ((unsigned)((int)t >> 31) | 0x80000000u);
    ull pk = ((ull)u0 << 7) | (unsigned)(127 - cls);
    { ull o = __shfl_xor_sync(0xffffffffu, pk, 1); pk = pk > o ? pk : o; }
    { ull o = __shfl_xor_sync(0xffffffffu, pk, 2); pk = pk > o ? pk : o; }

    if (j == 0) {                          // lanes 0,4,..,28 -> coalesced STG.64
        int qq = q0 + g;
        g_keys[b * NQ + qq] = ((ull)(pk >> 7) << 32)
                            | ((unsigned)(1023 - qq) << 8)
                            | (unsigned)(127 - (int)(pk & 0x7f));
    }
}

// ---------------------------------------------------------------------------
// Bitonic helper: sort 32 keys descending across lanes (15 stages).
// ---------------------------------------------------------------------------
__device__ __forceinline__ void shfl_sort32(ull& v, unsigned i) {
    #pragma unroll
    for (unsigned k = 2; k <= 32; k <<= 1) {
        #pragma unroll
        for (int j = 16; j >= 1; j >>= 1) {
            if ((unsigned)j < k) {
                ull pv = __shfl_xor_sync(0xffffffffu, v, j);
                bool keep_max = (((i & k) == 0) == ((i & (unsigned)j) == 0));
                v = keep_max ? (v > pv ? v : pv) : (v < pv ? v : pv);
            }
        }
    }
}

// ---------------------------------------------------------------------------
// Merge-path rank select (descending; keys unique via embedded query id).
// ---------------------------------------------------------------------------
__device__ __forceinline__ ull
rank_select(const ull* __restrict__ A, const ull* __restrict__ B,
            int r, int NA, int NBL) {
    int lo = r + 1 - NBL; if (lo < 0) lo = 0;
    int hi = r + 1;       if (hi > NA) hi = NA;
    while (lo < hi) {
        int i = (lo + hi) >> 1;
        if (B[r - i] > A[i]) hi = i; else lo = i + 1;
    }
    int is = lo, js = r + 1 - lo;
    ull ka = is ? A[is - 1] : 0xFFFFFFFFFFFFFFFFull;
    ull kb = js ? B[js - 1] : 0xFFFFFFFFFFFFFFFFull;
    return ka < kb ? ka : kb;
}

// ---------------------------------------------------------------------------
// Kernel 2: one block (1024 thr) per row. 32 per-warp register 32-sorts
// (15 shuffle stages, zero barriers), then 5-level merge-path tree
// (5 barriers), then epilogue.
// ---------------------------------------------------------------------------
__global__ void __launch_bounds__(1024) topk_kernel(const float* __restrict__ boxes,
                                                    const float* __restrict__ tsz,
                                                    float* __restrict__ out) {
    __shared__ ull BUF0[1024];
    __shared__ ull BUF1[1024];
    int b    = blockIdx.x;
    int tid  = threadIdx.x;
    int wid  = tid >> 5;
    int lane = tid & 31;

    // Per-warp 32-sort: warp w owns keys [w*32, w*32+32) of the padded row.
    {
        int e = wid * 32 + lane;
        ull v = (e < NQ) ? g_keys[b * NQ + e] : 0ull;
        shfl_sort32(v, (unsigned)lane);
        BUF0[tid] = v;
    }
    __syncthreads();

    // L1: 16 merges (32,32) -> 64  -> BUF1
    {
        int pair = tid >> 6, r = tid & 63;
        const ull* A = BUF0 + pair * 64;
        BUF1[tid] = rank_select(A, A + 32, r, 32, 32);
    }
    __syncthreads();

    // L2: 8 merges (64,64) -> 128 -> BUF0
    {
        int pair = tid >> 7, r = tid & 127;
        const ull* A = BUF1 + pair * 128;
        BUF0[tid] = rank_select(A, A + 64, r, 64, 64);
    }
    __syncthreads();

    // L3: 4 merges (128,128) -> 256 -> BUF1
    {
        int pair = tid >> 8, r = tid & 255;
        const ull* A = BUF0 + pair * 256;
        BUF1[tid] = rank_select(A, A + 128, r, 128, 128);
    }
    __syncthreads();

    // L4: 2 merges (256,256) -> top 300 each -> BUF0
    if (tid < 2 * TOPK) {
        int pair = tid / TOPK, r = tid - pair * TOPK;
        const ull* A = BUF1 + pair * 512;
        BUF0[pair * TOPK + r] = rank_select(A, A + 256, r, 256, 256);
    }
    __syncthreads();

    // L5: final (300,300) -> rank tid, then epilogue.
    if (tid < TOPK) {
        ull key = rank_select(BUF0, BUF0 + TOPK, tid, TOPK, TOPK);

        unsigned u = (unsigned)(key >> 32);
        float logit = (u & 0x80000000u) ? __uint_as_float(u ^ 0x80000000u)
                                        : __uint_as_float(~u);
        float score = 1.0f / (1.0f + expf(-logit));
        bool  valid = (score > 0.05f);

        unsigned lw = (unsigned)(key & 0xffffffffu);
        int qi    = 1023 - (int)((lw >> 8) & 0x3ffu);
        int label = (int)(lw & 0xffu);

        float4 bx = ((const float4*)boxes)[b * NQ + qi];
        float img_h = tsz[b * 2 + 0];
        float img_w = tsz[b * 2 + 1];
        float x0 = (bx.x - 0.5f * bx.z) * img_w;
        float y0 = (bx.y - 0.5f * bx.w) * img_h;
        float x1 = (bx.x + 0.5f * bx.z) * img_w;
        float y1 = (bx.y + 0.5f * bx.w) * img_h;

        float* out_scores = out;
        float* out_labels = out + NB * TOPK;
        float* out_boxes  = out + 2 * NB * TOPK;

        out_scores[b * TOPK + tid] = valid ? score : 0.0f;
        out_labels[b * TOPK + tid] = valid ? (float)label : -1.0f;
        float4 ob = valid ? make_float4(x0, y0, x1, y1)
                          : make_float4(0.f, 0.f, 0.f, 0.f);
        ((float4*)out_boxes)[b * TOPK + tid] = ob;
    }
}

// ---------------------------------------------------------------------------
extern "C" void kernel_launch(void* const* d_in, const int* in_sizes, int n_in,
                              void* d_out, int out_size) {
    const float* logits = (const float*)d_in[0];
    const float* boxes  = (const float*)d_in[1];
    const float* tsz    = (const float*)d_in[2];
    float* out = (float*)d_out;

    dim3 sgrid(16, NB);                    // 16 blocks x 64 queries per row
    score_kernel<<<sgrid, 256>>>(logits);
    topk_kernel<<<NB, 1024>>>(boxes, tsz, out);
}